// round 15
// baseline (speedup 1.0000x reference)
#include <cuda_runtime.h>

#define NB 8
#define NT 2048
#define NE 128
#define NH 16

// Q/K/V scratch + split-K partials (allocation-free: __device__ globals)
__device__ float g_Q[NB * NT * NH];
__device__ float g_K[NB * NT * NH];
__device__ float g_V[NB * NT * NH];
// partial state per (job=(b*32+qt)*8+kc, query): l, a[16]  (fixed softmax ref)
__device__ float g_pl[8 * 32 * 8 * 64];
__device__ float g_pa[8 * 32 * 8 * 64 * 16];

typedef unsigned long long u64;

#define MREF 12.0f   // fixed log2-domain softmax reference (|s| << 12 + 80 safe)

__device__ __forceinline__ float ex2f(float x) {
    float y;
    asm("ex2.approx.ftz.f32 %0, %1;" : "=f"(y) : "f"(x));
    return y;
}
// Blackwell packed fp32x2 (2x fp32 FMA throughput; ptxas never auto-fuses)
__device__ __forceinline__ u64 fma2(u64 a, u64 b, u64 c) {
    u64 d; asm("fma.rn.f32x2 %0, %1, %2, %3;" : "=l"(d) : "l"(a), "l"(b), "l"(c)); return d;
}
__device__ __forceinline__ u64 mul2(u64 a, u64 b) {
    u64 d; asm("mul.rn.f32x2 %0, %1, %2;" : "=l"(d) : "l"(a), "l"(b)); return d;
}
__device__ __forceinline__ u64 add2(u64 a, u64 b) {
    u64 d; asm("add.rn.f32x2 %0, %1, %2;" : "=l"(d) : "l"(a), "l"(b)); return d;
}
__device__ __forceinline__ u64 pack2(float lo, float hi) {
    u64 r; asm("mov.b64 %0, {%1,%2};" : "=l"(r) : "f"(lo), "f"(hi)); return r;
}
__device__ __forceinline__ void unpack2(u64 v, float& lo, float& hi) {
    asm("mov.b64 {%0,%1}, %2;" : "=f"(lo), "=f"(hi) : "l"(v));
}

// ---------------------------------------------------------------------------
// Kernel 1: fused QKV projection, G=4 tokens/thread, 12-col quarters.
// CTA = 64 tokens x 12 cols, grid 1024 = 256 tok-tiles x 4 col-quarters.
// Thread = (tokg = tid&15: tokens tokg+{0,16,32,48}, g = tid>>4: e-rows
// [g*16, g*16+16)). Per e-iter: 4 x-LDS (conflict-free) + 3 W-LDS.128
// (2 half-warp addresses, disjoint banks via stride-20 rows) -> 24 fma2.
// Merge: shfl_xor(16) within warp, then 3-warp smem stage.
// smem 43KB, grid 6.9 CTAs/SM -> occupancy 4.
// ---------------------------------------------------------------------------
__global__ __launch_bounds__(128, 4) void qkv_kernel(
    const float* __restrict__ x,
    const float* __restrict__ Wq,
    const float* __restrict__ Wk,
    const float* __restrict__ Wv)
{
    __shared__ float sXf[64 * 129];                // 33KB; reused as stage
    __shared__ __align__(16) float sWf[128 * 20];  // 10.2KB (12 cols + 8 pad)
    const int tid  = threadIdx.x;
    const int bid  = blockIdx.x;
    const int tok0 = (bid >> 2) * 64;
    const int colq = bid & 3;                      // which 12-col quarter

    // x tile: 64 tok x 32 f4 = 2048 f4, coalesced loads, scalar stores
    const float4* xg = reinterpret_cast<const float4*>(x) + (size_t)tok0 * 32;
#pragma unroll
    for (int i = 0; i < 16; i++) {
        int idx = i * 128 + tid;
        int tok = idx >> 5, e4 = idx & 31;
        float4 v = xg[idx];
        float* p = &sXf[tok * 129 + e4 * 4];
        p[0] = v.x; p[1] = v.y; p[2] = v.z; p[3] = v.w;
    }
    // W quarter: 128 e-rows x 12 cols = 384 f4 (row stride 20 floats = 80B)
    const float4* wq4 = reinterpret_cast<const float4*>(Wq);
    const float4* wk4 = reinterpret_cast<const float4*>(Wk);
    const float4* wv4 = reinterpret_cast<const float4*>(Wv);
#pragma unroll
    for (int i = 0; i < 3; i++) {
        int idx = i * 128 + tid;       // 0..383
        int e = idx / 3, c4 = idx % 3;
        int col = colq * 12 + c4 * 4;
        int m = col >> 4, h4 = (col & 15) >> 2;
        float4 w = (m == 0) ? wq4[e * 4 + h4]
                 : (m == 1) ? wk4[e * 4 + h4]
                            : wv4[e * 4 + h4];
        *reinterpret_cast<float4*>(&sWf[e * 20 + c4 * 4]) = w;
    }
    __syncthreads();

    const int tokg = tid & 15;           // tokens tokg + {0,16,32,48}
    const int g    = tid >> 4;           // e-group: rows [g*16, g*16+16)
    const float* xp0 = &sXf[tokg * 129];
    const float* xp1 = &sXf[(tokg + 16) * 129];
    const float* xp2 = &sXf[(tokg + 32) * 129];
    const float* xp3 = &sXf[(tokg + 48) * 129];

    u64 acc[24];                         // [6t..6t+5] = token t's 12 cols
#pragma unroll
    for (int i = 0; i < 24; i++) acc[i] = 0ull;

    const int e0 = g * 16;
#pragma unroll 4
    for (int ee = 0; ee < 16; ee++) {
        int e = e0 + ee;
        float a0 = xp0[e], a1 = xp1[e], a2 = xp2[e], a3 = xp3[e];
        const ulonglong2* wp = reinterpret_cast<const ulonglong2*>(
            &sWf[e * 20]);               // 2 half-warp addrs, disjoint banks
        ulonglong2 wa = wp[0], wb = wp[1], wc = wp[2];
        u64 x0 = pack2(a0, a0), x1 = pack2(a1, a1);
        u64 x2 = pack2(a2, a2), x3 = pack2(a3, a3);
        acc[0]  = fma2(x0, wa.x, acc[0]);
        acc[1]  = fma2(x0, wa.y, acc[1]);
        acc[2]  = fma2(x0, wb.x, acc[2]);
        acc[3]  = fma2(x0, wb.y, acc[3]);
        acc[4]  = fma2(x0, wc.x, acc[4]);
        acc[5]  = fma2(x0, wc.y, acc[5]);
        acc[6]  = fma2(x1, wa.x, acc[6]);
        acc[7]  = fma2(x1, wa.y, acc[7]);
        acc[8]  = fma2(x1, wb.x, acc[8]);
        acc[9]  = fma2(x1, wb.y, acc[9]);
        acc[10] = fma2(x1, wc.x, acc[10]);
        acc[11] = fma2(x1, wc.y, acc[11]);
        acc[12] = fma2(x2, wa.x, acc[12]);
        acc[13] = fma2(x2, wa.y, acc[13]);
        acc[14] = fma2(x2, wb.x, acc[14]);
        acc[15] = fma2(x2, wb.y, acc[15]);
        acc[16] = fma2(x2, wc.x, acc[16]);
        acc[17] = fma2(x2, wc.y, acc[17]);
        acc[18] = fma2(x3, wa.x, acc[18]);
        acc[19] = fma2(x3, wa.y, acc[19]);
        acc[20] = fma2(x3, wb.x, acc[20]);
        acc[21] = fma2(x3, wb.y, acc[21]);
        acc[22] = fma2(x3, wc.x, acc[22]);
        acc[23] = fma2(x3, wc.y, acc[23]);
    }

    // merge e-group pairs within warp: lane^16 holds e-range +16 of same tokg
    const unsigned FULL = 0xffffffffu;
#pragma unroll
    for (int j = 0; j < 24; j++)
        acc[j] = add2(acc[j], __shfl_xor_sync(FULL, acc[j], 16));

    __syncthreads();                     // x reads done -> reuse sXf as stage

    // merge 4 warp partials (e-ranges of 32 rows each): warps 1..3 lanes<16
    // stage 24 u64 (stride 25), warp 0 lanes<16 add.
    const int warp = tid >> 5;
    const int lane = tid & 31;
    u64* stage = reinterpret_cast<u64*>(sXf);
    if (warp > 0 && lane < 16) {
        int base = ((warp - 1) * 16 + lane) * 25;
#pragma unroll
        for (int j = 0; j < 24; j++) stage[base + j] = acc[j];
    }
    __syncthreads();

    if (warp == 0 && lane < 16) {
#pragma unroll
        for (int w = 0; w < 3; w++) {
            int base = (w * 16 + lane) * 25;
#pragma unroll
            for (int j = 0; j < 24; j++)
                acc[j] = add2(acc[j], stage[base + j]);
        }
        float av[48];
#pragma unroll
        for (int j = 0; j < 24; j++) unpack2(acc[j], av[2 * j], av[2 * j + 1]);
#pragma unroll
        for (int t = 0; t < 4; t++) {
            const int tok = tok0 + lane + t * 16;   // lane == tokg here
            const float* avt = av + t * 12;
#pragma unroll
            for (int k3 = 0; k3 < 3; k3++) {
                int c0 = colq * 12 + k3 * 4;  // 4-blocks never straddle matrices
                float* base_p = (c0 < 16) ? g_Q : (c0 < 32) ? g_K : g_V;
                float4 o = make_float4(avt[k3*4+0], avt[k3*4+1],
                                       avt[k3*4+2], avt[k3*4+3]);
                *reinterpret_cast<float4*>(base_p + (size_t)tok * NH + (c0 & 15)) = o;
            }
        }
    }
}

// ---------------------------------------------------------------------------
// Kernel 2: split-K causal flash attention (R7/R13 body, occupancy 4).
// FIXED-REFERENCE softmax (p = 2^(s-MREF)). Job = (b, qt, kc: 256-key chunk)
// -> 1152 jobs. Warp = key phase (pairs {2r,2r+1} mod 8 -> broadcast LDS),
// lane = query slot (owns qt*64+lane and +32). Dynamic-bound diagonal loop.
// ---------------------------------------------------------------------------
__device__ __forceinline__ void scores2(
    const ulonglong2* __restrict__ kp, const u64* __restrict__ q,
    float& s0a, float& s1a, float& s0b, float& s1b)
{
    ulonglong2 a0 = kp[0], a1 = kp[1], a2 = kp[2], a3 = kp[3];
    ulonglong2 b0 = kp[4], b1 = kp[5], b2 = kp[6], b3 = kp[7];
    u64 t; float lo, hi;
    t = fma2(q[0], a0.x, fma2(q[2], a1.x, fma2(q[4], a2.x, mul2(q[6],  a3.x))));
    t = add2(t, fma2(q[1], a0.y, fma2(q[3], a1.y, fma2(q[5], a2.y, mul2(q[7],  a3.y)))));
    unpack2(t, lo, hi); s0a = lo + hi;
    t = fma2(q[8], a0.x, fma2(q[10],a1.x, fma2(q[12],a2.x, mul2(q[14], a3.x))));
    t = add2(t, fma2(q[9], a0.y, fma2(q[11],a1.y, fma2(q[13],a2.y, mul2(q[15], a3.y)))));
    unpack2(t, lo, hi); s1a = lo + hi;
    t = fma2(q[0], b0.x, fma2(q[2], b1.x, fma2(q[4], b2.x, mul2(q[6],  b3.x))));
    t = add2(t, fma2(q[1], b0.y, fma2(q[3], b1.y, fma2(q[5], b2.y, mul2(q[7],  b3.y)))));
    unpack2(t, lo, hi); s0b = lo + hi;
    t = fma2(q[8], b0.x, fma2(q[10],b1.x, fma2(q[12],b2.x, mul2(q[14], b3.x))));
    t = add2(t, fma2(q[9], b0.y, fma2(q[11],b1.y, fma2(q[13],b2.y, mul2(q[15], b3.y)))));
    unpack2(t, lo, hi); s1b = lo + hi;
}

template<bool MASKED>
__device__ __forceinline__ void updF(
    float sa, float sb, bool oka, bool okb,
    float& l, u64* __restrict__ a,
    const ulonglong2& va0, const ulonglong2& va1,
    const ulonglong2& va2, const ulonglong2& va3,
    const ulonglong2& vb0, const ulonglong2& vb1,
    const ulonglong2& vb2, const ulonglong2& vb3)
{
    float pa = ex2f(sa - MREF);
    float pb = ex2f(sb - MREF);
    if (MASKED) {                 // FSEL, no branch
        pa = oka ? pa : 0.f;
        pb = okb ? pb : 0.f;
    }
    l += pa + pb;
    u64 pap = pack2(pa, pa), pbp = pack2(pb, pb);
    a[0] = fma2(pap, va0.x, fma2(pbp, vb0.x, a[0]));
    a[1] = fma2(pap, va0.y, fma2(pbp, vb0.y, a[1]));
    a[2] = fma2(pap, va1.x, fma2(pbp, vb1.x, a[2]));
    a[3] = fma2(pap, va1.y, fma2(pbp, vb1.y, a[3]));
    a[4] = fma2(pap, va2.x, fma2(pbp, vb2.x, a[4]));
    a[5] = fma2(pap, va2.y, fma2(pbp, vb2.y, a[5]));
    a[6] = fma2(pap, va3.x, fma2(pbp, vb3.x, a[6]));
    a[7] = fma2(pap, va3.y, fma2(pbp, vb3.y, a[7]));
}

__global__ __launch_bounds__(128, 4) void attn_kernel()
{
    __shared__ float4 sbuf[1024];    // K[512] | V[512]; reused for combine
    float4* sK4 = sbuf;
    float4* sV4 = sbuf + 512;

    // job decode: groups g=7..0 (qt in [4g,4g+4), g+1 chunks per qt), heavy first
    const int bid = blockIdx.x;           // 0..1151
    const int b   = bid & 7;
    int rem = bid >> 3;                   // 0..143
    int g = 7;
    while (rem >= 4 * (g + 1)) { rem -= 4 * (g + 1); g--; }
    const int qt = 4 * g + rem / (g + 1);
    const int kc = rem % (g + 1);

    const int tid  = threadIdx.x;
    const int r    = tid >> 5;            // warp id = key-pair phase (uniform)
    const int lane = tid & 31;            // query slot
    const int qg0  = qt * 64 + lane;
    const int qg1  = qg0 + 32;
    const int ks0  = kc << 8;             // 256-key chunk base
    const int ttot = (qt >> 1) + 1;       // total 128-key tiles for this qt
    const int ntiles = min(2, ttot - 2 * kc);

    const float SC = 0.25f * 1.44269504088896340736f;  // H^-0.5 * log2(e)
    u64 q[16];
    {
        const float4* qp0 = reinterpret_cast<const float4*>(g_Q + ((size_t)b * NT + qg0) * NH);
        const float4* qp1 = reinterpret_cast<const float4*>(g_Q + ((size_t)b * NT + qg1) * NH);
#pragma unroll
        for (int i = 0; i < 4; i++) {
            float4 t0 = qp0[i], t1 = qp1[i];
            q[2*i]     = pack2(t0.x * SC, t0.y * SC);
            q[2*i+1]   = pack2(t0.z * SC, t0.w * SC);
            q[8+2*i]   = pack2(t1.x * SC, t1.y * SC);
            q[8+2*i+1] = pack2(t1.z * SC, t1.w * SC);
        }
    }

    float l0 = 0.f, l1 = 0.f;
    u64 a[16];
#pragma unroll
    for (int i = 0; i < 16; i++) a[i] = 0ull;

    const float4* Kg = reinterpret_cast<const float4*>(g_K + (size_t)b * NT * NH);
    const float4* Vg = reinterpret_cast<const float4*>(g_V + (size_t)b * NT * NH);
    const ulonglong2* sK2 = reinterpret_cast<const ulonglong2*>(sK4);
    const ulonglong2* sV2 = reinterpret_cast<const ulonglong2*>(sV4);

    for (int kt = 0; kt < ntiles; kt++) {
        const int kb = ks0 + (kt << 7);   // tile key base
#pragma unroll
        for (int i = 0; i < 4; i++) {
            int idx = i * 128 + tid;
            sK4[idx] = Kg[(size_t)kb * 4 + idx];
            sV4[idx] = Vg[(size_t)kb * 4 + idx];
        }
        __syncthreads();

        if (kb + 127 <= qt * 64) {
            // full tile: 16 key-pairs per warp, no masks
#pragma unroll 4
            for (int jj = 0; jj < 16; jj++) {
                int j0 = 8 * jj + 2 * r;          // warp-uniform
                float s0a, s1a, s0b, s1b;
                scores2(sK2 + j0 * 4, q, s0a, s1a, s0b, s1b);
                const ulonglong2* vp = sV2 + j0 * 4;
                ulonglong2 va0 = vp[0], va1 = vp[1], va2 = vp[2], va3 = vp[3];
                ulonglong2 vb0 = vp[4], vb1 = vp[5], vb2 = vp[6], vb3 = vp[7];
                updF<false>(s0a, s0b, true, true, l0, a,
                            va0, va1, va2, va3, vb0, vb1, vb2, vb3);
                updF<false>(s1a, s1b, true, true, l1, a + 8,
                            va0, va1, va2, va3, vb0, vb1, vb2, vb3);
            }
        } else {
            // diagonal tile: per-lane causal masks via FSEL (p zeroed)
            const int jmax = min(127, qt * 64 + 63 - kb);
            for (int j0 = 2 * r; j0 <= jmax; j0 += 8) {
                float s0a, s1a, s0b, s1b;
                scores2(sK2 + j0 * 4, q, s0a, s1a, s0b, s1b);
                const ulonglong2* vp = sV2 + j0 * 4;
                ulonglong2 va0 = vp[0], va1 = vp[1], va2 = vp[2], va3 = vp[3];
                ulonglong2 vb0 = vp[4], vb1 = vp[5], vb2 = vp[6], vb3 = vp[7];
                int kja = kb + j0, kjb = kja + 1;
                updF<true>(s0a, s0b, kja <= qg0, kjb <= qg0, l0, a,
                           va0, va1, va2, va3, vb0, vb1, vb2, vb3);
                updF<true>(s1a, s1b, kja <= qg1, kjb <= qg1, l1, a + 8,
                           va0, va1, va2, va3, vb0, vb1, vb2, vb3);
            }
        }
        __syncthreads();
    }

    // cross-warp combine (fixed reference -> plain sums): warps 1..3 stage,
    // warp 0 adds. stride-5 ulonglong2 layout, conflict-free.
    ulonglong2* cb = reinterpret_cast<ulonglong2*>(sbuf);
    if (r > 0) {
#pragma unroll
        for (int qi = 0; qi < 2; qi++) {
            int base = ((r - 1) * 2 + qi) * 160 + lane * 5;
            const u64* aq = a + qi * 8;
            cb[base + 0] = make_ulonglong2(aq[0], aq[1]);
            cb[base + 1] = make_ulonglong2(aq[2], aq[3]);
            cb[base + 2] = make_ulonglong2(aq[4], aq[5]);
            cb[base + 3] = make_ulonglong2(aq[6], aq[7]);
            cb[base + 4] = make_ulonglong2(pack2(qi == 0 ? l0 : l1, 0.f), 0ull);
        }
    }
    __syncthreads();

    if (r == 0) {
#pragma unroll
        for (int w = 1; w < 4; w++) {
#pragma unroll
            for (int qi = 0; qi < 2; qi++) {
                int base = ((w - 1) * 2 + qi) * 160 + lane * 5;
                float lw, dummy;
                unpack2(cb[base + 4].x, lw, dummy);
                if (qi == 0) l0 += lw; else l1 += lw;
                u64* aq = a + qi * 8;
#pragma unroll
                for (int i = 0; i < 4; i++) {
                    ulonglong2 t = cb[base + i];
                    aq[2*i]   = add2(aq[2*i],   t.x);
                    aq[2*i+1] = add2(aq[2*i+1], t.y);
                }
            }
        }
        // emit split-K partial (shared fixed reference -> just l and a)
        const int jid = ((b * 32 + qt) << 3) + kc;
        g_pl[jid * 64 + lane]      = l0;
        g_pl[jid * 64 + lane + 32] = l1;
        float oc[32];
#pragma unroll
        for (int i = 0; i < 8; i++) {
            unpack2(a[i],     oc[2*i],    oc[2*i+1]);
            unpack2(a[i + 8], oc[16+2*i], oc[16+2*i+1]);
        }
        float4* p0 = reinterpret_cast<float4*>(&g_pa[(size_t)(jid * 64 + lane) * 16]);
        float4* p1 = reinterpret_cast<float4*>(&g_pa[(size_t)(jid * 64 + lane + 32) * 16]);
#pragma unroll
        for (int i = 0; i < 4; i++) {
            p0[i] = make_float4(oc[4*i],    oc[4*i+1],    oc[4*i+2],    oc[4*i+3]);
            p1[i] = make_float4(oc[16+4*i], oc[16+4*i+1], oc[16+4*i+2], oc[16+4*i+3]);
        }
    }
}

// ---------------------------------------------------------------------------
// Kernel 3: sum <=8 split-K partials per query (shared reference) + normalize.
// ---------------------------------------------------------------------------
__global__ __launch_bounds__(64, 8) void combine_kernel(float* __restrict__ out)
{
    const int bq = blockIdx.x;            // 0..255
    const int b  = bq >> 5, qt = bq & 31;
    const int ql = threadIdx.x;           // 0..63
    const int nc = (qt >> 2) + 1;
    const int base = (b * 32 + qt) << 3;

    float L = 0.f;
    float acc[16];
#pragma unroll
    for (int i = 0; i < 16; i++) acc[i] = 0.f;

    for (int c = 0; c < nc; c++) {
        L += g_pl[(base + c) * 64 + ql];
        const float4* pa = reinterpret_cast<const float4*>(
            &g_pa[(size_t)((base + c) * 64 + ql) * 16]);
#pragma unroll
        for (int i = 0; i < 4; i++) {
            float4 v = pa[i];
            acc[4*i+0] += v.x;
            acc[4*i+1] += v.y;
            acc[4*i+2] += v.z;
            acc[4*i+3] += v.w;
        }
    }
    float inv = 1.0f / L;
    float4* op = reinterpret_cast<float4*>(out + ((size_t)b * NT + qt * 64 + ql) * NH);
#pragma unroll
    for (int i = 0; i < 4; i++)
        op[i] = make_float4(acc[4*i] * inv, acc[4*i+1] * inv,
                            acc[4*i+2] * inv, acc[4*i+3] * inv);
}

extern "C" void kernel_launch(void* const* d_in, const int* in_sizes, int n_in,
                              void* d_out, int out_size)
{
    const float* x  = (const float*)d_in[0];
    const float* Wq = (const float*)d_in[1];
    const float* Wk = (const float*)d_in[2];
    const float* Wv = (const float*)d_in[3];
    float* out = (float*)d_out;

    qkv_kernel<<<1024, 128>>>(x, Wq, Wk, Wv);  // 256 tok-tiles x 4 col-quarters
    attn_kernel<<<1152, 128>>>();              // 256-key split-K jobs
    combine_kernel<<<256, 64>>>(out);          // sum + normalize
}

// round 16
// speedup vs baseline: 1.0907x; 1.0907x over previous
#include <cuda_runtime.h>

#define NB 8
#define NT 2048
#define NE 128
#define NH 16

// Q/K/V scratch + split-K partials (allocation-free: __device__ globals)
__device__ float g_Q[NB * NT * NH];
__device__ float g_K[NB * NT * NH];
__device__ float g_V[NB * NT * NH];
// partial state per (job=(b*32+qt)*8+kc, query): l, a[16]  (fixed softmax ref)
__device__ float g_pl[8 * 32 * 8 * 64];
__device__ float g_pa[8 * 32 * 8 * 64 * 16];

typedef unsigned long long u64;

#define MREF 12.0f   // fixed log2-domain softmax reference (|s| << 12 + 80 safe)

__device__ __forceinline__ float ex2f(float x) {
    float y;
    asm("ex2.approx.ftz.f32 %0, %1;" : "=f"(y) : "f"(x));
    return y;
}
// Blackwell packed fp32x2 (2x fp32 FMA throughput; ptxas never auto-fuses)
__device__ __forceinline__ u64 fma2(u64 a, u64 b, u64 c) {
    u64 d; asm("fma.rn.f32x2 %0, %1, %2, %3;" : "=l"(d) : "l"(a), "l"(b), "l"(c)); return d;
}
__device__ __forceinline__ u64 mul2(u64 a, u64 b) {
    u64 d; asm("mul.rn.f32x2 %0, %1, %2;" : "=l"(d) : "l"(a), "l"(b)); return d;
}
__device__ __forceinline__ u64 add2(u64 a, u64 b) {
    u64 d; asm("add.rn.f32x2 %0, %1, %2;" : "=l"(d) : "l"(a), "l"(b)); return d;
}
__device__ __forceinline__ u64 pack2(float lo, float hi) {
    u64 r; asm("mov.b64 %0, {%1,%2};" : "=l"(r) : "f"(lo), "f"(hi)); return r;
}
__device__ __forceinline__ void unpack2(u64 v, float& lo, float& hi) {
    asm("mov.b64 {%0,%1}, %2;" : "=f"(lo), "=f"(hi) : "l"(v));
}
__device__ __forceinline__ unsigned smem_u32(const void* p) {
    unsigned a;
    asm("{ .reg .u64 t; cvta.to.shared.u64 t, %1; cvt.u32.u64 %0, t; }"
        : "=r"(a) : "l"(p));
    return a;
}
__device__ __forceinline__ void cp_async16(unsigned dst, const void* src) {
    asm volatile("cp.async.cg.shared.global [%0], [%1], 16;"
                 :: "r"(dst), "l"(src));
}

// ---------------------------------------------------------------------------
// Kernel 1: fused QKV projection, G=4 tokens/thread (R12/R13, measured 14.0).
// CTA = 64 tokens x 24 cols (half of Wq|Wk|Wv), grid 512 = 256 tok-tiles x 2.
// Per e-iter: 4 x-LDS + 3 W-LDS.128 = 7 LSU wavefronts feeding 24 fma2.
// ---------------------------------------------------------------------------
__global__ __launch_bounds__(128, 4) void qkv_kernel(
    const float* __restrict__ x,
    const float* __restrict__ Wq,
    const float* __restrict__ Wk,
    const float* __restrict__ Wv)
{
    __shared__ float sXf[64 * 129];                // 33KB; reused as stage
    __shared__ __align__(16) float sWf[128 * 28];  // 14KB (24 cols + 4 pad)
    const int tid  = threadIdx.x;
    const int bid  = blockIdx.x;
    const int tok0 = (bid >> 1) * 64;
    const int colh = bid & 1;                      // which 24-col half

    // x tile: 64 tok x 32 f4 = 2048 f4, coalesced loads, scalar stores
    const float4* xg = reinterpret_cast<const float4*>(x) + (size_t)tok0 * 32;
#pragma unroll
    for (int i = 0; i < 16; i++) {
        int idx = i * 128 + tid;
        int tok = idx >> 5, e4 = idx & 31;
        float4 v = xg[idx];
        float* p = &sXf[tok * 129 + e4 * 4];
        p[0] = v.x; p[1] = v.y; p[2] = v.z; p[3] = v.w;
    }
    // W half: 128 e-rows x 24 cols = 768 f4 (row stride 28 floats, 16B-aligned)
    const float4* wq4 = reinterpret_cast<const float4*>(Wq);
    const float4* wk4 = reinterpret_cast<const float4*>(Wk);
    const float4* wv4 = reinterpret_cast<const float4*>(Wv);
#pragma unroll
    for (int i = 0; i < 6; i++) {
        int idx = i * 128 + tid;       // 0..767
        int e = idx / 6, c4 = idx % 6;
        int col = colh * 24 + c4 * 4;
        int m = col >> 4, h4 = (col & 15) >> 2;
        float4 w = (m == 0) ? wq4[e * 4 + h4]
                 : (m == 1) ? wk4[e * 4 + h4]
                            : wv4[e * 4 + h4];
        *reinterpret_cast<float4*>(&sWf[e * 28 + c4 * 4]) = w;
    }
    __syncthreads();

    const int tokg = tid & 15;           // tokens tokg + {0,16,32,48}
    const int colg = (tid >> 4) & 1;     // 12 cols (half-warp uniform)
    const int eq   = tid >> 5;           // e-quarter (warp-uniform)
    const float* xp0 = &sXf[tokg * 129];
    const float* xp1 = &sXf[(tokg + 16) * 129];
    const float* xp2 = &sXf[(tokg + 32) * 129];
    const float* xp3 = &sXf[(tokg + 48) * 129];

    u64 acc[24];                         // [6t..6t+5] = token t's 12 cols
#pragma unroll
    for (int i = 0; i < 24; i++) acc[i] = 0ull;

    const int e0 = eq * 32;
#pragma unroll 4
    for (int ee = 0; ee < 32; ee++) {
        int e = e0 + ee;
        float a0 = xp0[e], a1 = xp1[e], a2 = xp2[e], a3 = xp3[e];
        const ulonglong2* wp = reinterpret_cast<const ulonglong2*>(
            &sWf[e * 28 + colg * 12]);   // 2-address broadcast LDS.128
        ulonglong2 wa = wp[0], wb = wp[1], wc = wp[2];
        u64 x0 = pack2(a0, a0), x1 = pack2(a1, a1);
        u64 x2 = pack2(a2, a2), x3 = pack2(a3, a3);
        acc[0]  = fma2(x0, wa.x, acc[0]);
        acc[1]  = fma2(x0, wa.y, acc[1]);
        acc[2]  = fma2(x0, wb.x, acc[2]);
        acc[3]  = fma2(x0, wb.y, acc[3]);
        acc[4]  = fma2(x0, wc.x, acc[4]);
        acc[5]  = fma2(x0, wc.y, acc[5]);
        acc[6]  = fma2(x1, wa.x, acc[6]);
        acc[7]  = fma2(x1, wa.y, acc[7]);
        acc[8]  = fma2(x1, wb.x, acc[8]);
        acc[9]  = fma2(x1, wb.y, acc[9]);
        acc[10] = fma2(x1, wc.x, acc[10]);
        acc[11] = fma2(x1, wc.y, acc[11]);
        acc[12] = fma2(x2, wa.x, acc[12]);
        acc[13] = fma2(x2, wa.y, acc[13]);
        acc[14] = fma2(x2, wb.x, acc[14]);
        acc[15] = fma2(x2, wb.y, acc[15]);
        acc[16] = fma2(x2, wc.x, acc[16]);
        acc[17] = fma2(x2, wc.y, acc[17]);
        acc[18] = fma2(x3, wa.x, acc[18]);
        acc[19] = fma2(x3, wa.y, acc[19]);
        acc[20] = fma2(x3, wb.x, acc[20]);
        acc[21] = fma2(x3, wb.y, acc[21]);
        acc[22] = fma2(x3, wc.x, acc[22]);
        acc[23] = fma2(x3, wc.y, acc[23]);
    }
    __syncthreads();                     // x reads done -> reuse sXf as stage

    // merge 4 e-quarters: eq>0 warps stage (24 u64, stride 25), eq0 warp adds
    u64* stage = reinterpret_cast<u64*>(sXf);
    if (eq > 0) {
        int base = ((eq - 1) * 32 + (tid & 31)) * 25;
#pragma unroll
        for (int j = 0; j < 24; j++) stage[base + j] = acc[j];
    }
    __syncthreads();

    if (eq == 0) {
#pragma unroll
        for (int w = 0; w < 3; w++) {
            int base = (w * 32 + tid) * 25;
#pragma unroll
            for (int j = 0; j < 24; j++)
                acc[j] = add2(acc[j], stage[base + j]);
        }
        float av[48];
#pragma unroll
        for (int j = 0; j < 24; j++) unpack2(acc[j], av[2 * j], av[2 * j + 1]);
#pragma unroll
        for (int t = 0; t < 4; t++) {
            const int tok = tok0 + tokg + t * 16;
            const float* avt = av + t * 12;
#pragma unroll
            for (int k3 = 0; k3 < 3; k3++) {
                int c0 = colh * 24 + colg * 12 + k3 * 4;  // 4-blocks never straddle
                float* base_p = (c0 < 16) ? g_Q : (c0 < 32) ? g_K : g_V;
                float4 o = make_float4(avt[k3*4+0], avt[k3*4+1],
                                       avt[k3*4+2], avt[k3*4+3]);
                *reinterpret_cast<float4*>(base_p + (size_t)tok * NH + (c0 & 15)) = o;
            }
        }
    }
}

// ---------------------------------------------------------------------------
// Kernel 2: split-K causal flash attention (R13 body) + cp.async
// double-buffered K/V tiles (tile-1 load overlaps tile-0 compute).
// FIXED-REFERENCE softmax. Job = (b, qt, kc: 256-key chunk) -> 1152 jobs.
// Warp = key phase, lane = query slot (owns qt*64+lane and +32).
// ---------------------------------------------------------------------------
__device__ __forceinline__ void scores2(
    const ulonglong2* __restrict__ kp, const u64* __restrict__ q,
    float& s0a, float& s1a, float& s0b, float& s1b)
{
    ulonglong2 a0 = kp[0], a1 = kp[1], a2 = kp[2], a3 = kp[3];
    ulonglong2 b0 = kp[4], b1 = kp[5], b2 = kp[6], b3 = kp[7];
    u64 t; float lo, hi;
    t = fma2(q[0], a0.x, fma2(q[2], a1.x, fma2(q[4], a2.x, mul2(q[6],  a3.x))));
    t = add2(t, fma2(q[1], a0.y, fma2(q[3], a1.y, fma2(q[5], a2.y, mul2(q[7],  a3.y)))));
    unpack2(t, lo, hi); s0a = lo + hi;
    t = fma2(q[8], a0.x, fma2(q[10],a1.x, fma2(q[12],a2.x, mul2(q[14], a3.x))));
    t = add2(t, fma2(q[9], a0.y, fma2(q[11],a1.y, fma2(q[13],a2.y, mul2(q[15], a3.y)))));
    unpack2(t, lo, hi); s1a = lo + hi;
    t = fma2(q[0], b0.x, fma2(q[2], b1.x, fma2(q[4], b2.x, mul2(q[6],  b3.x))));
    t = add2(t, fma2(q[1], b0.y, fma2(q[3], b1.y, fma2(q[5], b2.y, mul2(q[7],  b3.y)))));
    unpack2(t, lo, hi); s0b = lo + hi;
    t = fma2(q[8], b0.x, fma2(q[10],b1.x, fma2(q[12],b2.x, mul2(q[14], b3.x))));
    t = add2(t, fma2(q[9], b0.y, fma2(q[11],b1.y, fma2(q[13],b2.y, mul2(q[15], b3.y)))));
    unpack2(t, lo, hi); s1b = lo + hi;
}

template<bool MASKED>
__device__ __forceinline__ void updF(
    float sa, float sb, bool oka, bool okb,
    float& l, u64* __restrict__ a,
    const ulonglong2& va0, const ulonglong2& va1,
    const ulonglong2& va2, const ulonglong2& va3,
    const ulonglong2& vb0, const ulonglong2& vb1,
    const ulonglong2& vb2, const ulonglong2& vb3)
{
    float pa = ex2f(sa - MREF);
    float pb = ex2f(sb - MREF);
    if (MASKED) {                 // FSEL, no branch
        pa = oka ? pa : 0.f;
        pb = okb ? pb : 0.f;
    }
    l += pa + pb;
    u64 pap = pack2(pa, pa), pbp = pack2(pb, pb);
    a[0] = fma2(pap, va0.x, fma2(pbp, vb0.x, a[0]));
    a[1] = fma2(pap, va0.y, fma2(pbp, vb0.y, a[1]));
    a[2] = fma2(pap, va1.x, fma2(pbp, vb1.x, a[2]));
    a[3] = fma2(pap, va1.y, fma2(pbp, vb1.y, a[3]));
    a[4] = fma2(pap, va2.x, fma2(pbp, vb2.x, a[4]));
    a[5] = fma2(pap, va2.y, fma2(pbp, vb2.y, a[5]));
    a[6] = fma2(pap, va3.x, fma2(pbp, vb3.x, a[6]));
    a[7] = fma2(pap, va3.y, fma2(pbp, vb3.y, a[7]));
}

// compute one 128-key tile from smem buffer (K at buf[0..511], V at buf[512..])
__device__ __forceinline__ void compute_tile(
    const float4* buf, int kb, int qt, int qg0, int qg1, int r,
    const u64* __restrict__ q, float& l0, float& l1, u64* __restrict__ a)
{
    const ulonglong2* sK2 = reinterpret_cast<const ulonglong2*>(buf);
    const ulonglong2* sV2 = reinterpret_cast<const ulonglong2*>(buf + 512);

    if (kb + 127 <= qt * 64) {
        // full tile: 16 key-pairs per warp, no masks
#pragma unroll 4
        for (int jj = 0; jj < 16; jj++) {
            int j0 = 8 * jj + 2 * r;          // warp-uniform
            float s0a, s1a, s0b, s1b;
            scores2(sK2 + j0 * 4, q, s0a, s1a, s0b, s1b);
            const ulonglong2* vp = sV2 + j0 * 4;
            ulonglong2 va0 = vp[0], va1 = vp[1], va2 = vp[2], va3 = vp[3];
            ulonglong2 vb0 = vp[4], vb1 = vp[5], vb2 = vp[6], vb3 = vp[7];
            updF<false>(s0a, s0b, true, true, l0, a,
                        va0, va1, va2, va3, vb0, vb1, vb2, vb3);
            updF<false>(s1a, s1b, true, true, l1, a + 8,
                        va0, va1, va2, va3, vb0, vb1, vb2, vb3);
        }
    } else {
        // diagonal tile: per-lane causal masks via FSEL (p zeroed)
        const int jmax = min(127, qt * 64 + 63 - kb);
        for (int j0 = 2 * r; j0 <= jmax; j0 += 8) {
            float s0a, s1a, s0b, s1b;
            scores2(sK2 + j0 * 4, q, s0a, s1a, s0b, s1b);
            const ulonglong2* vp = sV2 + j0 * 4;
            ulonglong2 va0 = vp[0], va1 = vp[1], va2 = vp[2], va3 = vp[3];
            ulonglong2 vb0 = vp[4], vb1 = vp[5], vb2 = vp[6], vb3 = vp[7];
            int kja = kb + j0, kjb = kja + 1;
            updF<true>(s0a, s0b, kja <= qg0, kjb <= qg0, l0, a,
                       va0, va1, va2, va3, vb0, vb1, vb2, vb3);
            updF<true>(s1a, s1b, kja <= qg1, kjb <= qg1, l1, a + 8,
                       va0, va1, va2, va3, vb0, vb1, vb2, vb3);
        }
    }
}

__global__ __launch_bounds__(128, 3) void attn_kernel()
{
    __shared__ float4 sbuf[2048];    // two 16KB tile buffers; buf0 reused for combine

    // job decode: groups g=7..0 (qt in [4g,4g+4), g+1 chunks per qt), heavy first
    const int bid = blockIdx.x;           // 0..1151
    const int b   = bid & 7;
    int rem = bid >> 3;                   // 0..143
    int g = 7;
    while (rem >= 4 * (g + 1)) { rem -= 4 * (g + 1); g--; }
    const int qt = 4 * g + rem / (g + 1);
    const int kc = rem % (g + 1);

    const int tid  = threadIdx.x;
    const int r    = tid >> 5;            // warp id = key-pair phase (uniform)
    const int lane = tid & 31;            // query slot
    const int qg0  = qt * 64 + lane;
    const int qg1  = qg0 + 32;
    const int ks0  = kc << 8;             // 256-key chunk base
    const int ttot = (qt >> 1) + 1;       // total 128-key tiles for this qt
    const int ntiles = min(2, ttot - 2 * kc);

    const float4* Kg = reinterpret_cast<const float4*>(g_K + (size_t)b * NT * NH);
    const float4* Vg = reinterpret_cast<const float4*>(g_V + (size_t)b * NT * NH);

    // issue async loads FIRST (overlap with Q load + setup)
    const unsigned sb0 = smem_u32(sbuf);
    const unsigned sb1 = sb0 + 16384;
#pragma unroll
    for (int i = 0; i < 4; i++) {
        int idx = i * 128 + tid;
        cp_async16(sb0 + idx * 16,          Kg + (size_t)ks0 * 4 + idx);
        cp_async16(sb0 + (512 + idx) * 16,  Vg + (size_t)ks0 * 4 + idx);
    }
    asm volatile("cp.async.commit_group;" ::: "memory");
    if (ntiles == 2) {
#pragma unroll
        for (int i = 0; i < 4; i++) {
            int idx = i * 128 + tid;
            cp_async16(sb1 + idx * 16,          Kg + (size_t)(ks0 + 128) * 4 + idx);
            cp_async16(sb1 + (512 + idx) * 16,  Vg + (size_t)(ks0 + 128) * 4 + idx);
        }
        asm volatile("cp.async.commit_group;" ::: "memory");
    }

    const float SC = 0.25f * 1.44269504088896340736f;  // H^-0.5 * log2(e)
    u64 q[16];
    {
        const float4* qp0 = reinterpret_cast<const float4*>(g_Q + ((size_t)b * NT + qg0) * NH);
        const float4* qp1 = reinterpret_cast<const float4*>(g_Q + ((size_t)b * NT + qg1) * NH);
#pragma unroll
        for (int i = 0; i < 4; i++) {
            float4 t0 = qp0[i], t1 = qp1[i];
            q[2*i]     = pack2(t0.x * SC, t0.y * SC);
            q[2*i+1]   = pack2(t0.z * SC, t0.w * SC);
            q[8+2*i]   = pack2(t1.x * SC, t1.y * SC);
            q[8+2*i+1] = pack2(t1.z * SC, t1.w * SC);
        }
    }

    float l0 = 0.f, l1 = 0.f;
    u64 a[16];
#pragma unroll
    for (int i = 0; i < 16; i++) a[i] = 0ull;

    // tile 0: wait for its group (1 group may still be pending behind it)
    if (ntiles == 2) {
        asm volatile("cp.async.wait_group 1;" ::: "memory");
    } else {
        asm volatile("cp.async.wait_group 0;" ::: "memory");
    }
    __syncthreads();
    compute_tile(sbuf, ks0, qt, qg0, qg1, r, q, l0, l1, a);

    if (ntiles == 2) {
        asm volatile("cp.async.wait_group 0;" ::: "memory");
        __syncthreads();                 // also separates tile-0 readers
        compute_tile(sbuf + 1024, ks0 + 128, qt, qg0, qg1, r, q, l0, l1, a);
    }
    __syncthreads();                     // all compute done -> reuse buf0

    // cross-warp combine (fixed reference -> plain sums): warps 1..3 stage,
    // warp 0 adds. stride-5 ulonglong2 layout, conflict-free.
    ulonglong2* cb = reinterpret_cast<ulonglong2*>(sbuf);
    if (r > 0) {
#pragma unroll
        for (int qi = 0; qi < 2; qi++) {
            int base = ((r - 1) * 2 + qi) * 160 + lane * 5;
            const u64* aq = a + qi * 8;
            cb[base + 0] = make_ulonglong2(aq[0], aq[1]);
            cb[base + 1] = make_ulonglong2(aq[2], aq[3]);
            cb[base + 2] = make_ulonglong2(aq[4], aq[5]);
            cb[base + 3] = make_ulonglong2(aq[6], aq[7]);
            cb[base + 4] = make_ulonglong2(pack2(qi == 0 ? l0 : l1, 0.f), 0ull);
        }
    }
    __syncthreads();

    if (r == 0) {
#pragma unroll
        for (int w = 1; w < 4; w++) {
#pragma unroll
            for (int qi = 0; qi < 2; qi++) {
                int base = ((w - 1) * 2 + qi) * 160 + lane * 5;
                float lw, dummy;
                unpack2(cb[base + 4].x, lw, dummy);
                if (qi == 0) l0 += lw; else l1 += lw;
                u64* aq = a + qi * 8;
#pragma unroll
                for (int i = 0; i < 4; i++) {
                    ulonglong2 t = cb[base + i];
                    aq[2*i]   = add2(aq[2*i],   t.x);
                    aq[2*i+1] = add2(aq[2*i+1], t.y);
                }
            }
        }
        // emit split-K partial (shared fixed reference -> just l and a)
        const int jid = ((b * 32 + qt) << 3) + kc;
        g_pl[jid * 64 + lane]      = l0;
        g_pl[jid * 64 + lane + 32] = l1;
        float oc[32];
#pragma unroll
        for (int i = 0; i < 8; i++) {
            unpack2(a[i],     oc[2*i],    oc[2*i+1]);
            unpack2(a[i + 8], oc[16+2*i], oc[16+2*i+1]);
        }
        float4* p0 = reinterpret_cast<float4*>(&g_pa[(size_t)(jid * 64 + lane) * 16]);
        float4* p1 = reinterpret_cast<float4*>(&g_pa[(size_t)(jid * 64 + lane + 32) * 16]);
#pragma unroll
        for (int i = 0; i < 4; i++) {
            p0[i] = make_float4(oc[4*i],    oc[4*i+1],    oc[4*i+2],    oc[4*i+3]);
            p1[i] = make_float4(oc[16+4*i], oc[16+4*i+1], oc[16+4*i+2], oc[16+4*i+3]);
        }
    }
}

// ---------------------------------------------------------------------------
// Kernel 3: sum <=8 split-K partials per query (shared reference) + normalize.
// ---------------------------------------------------------------------------
__global__ __launch_bounds__(64, 8) void combine_kernel(float* __restrict__ out)
{
    const int bq = blockIdx.x;            // 0..255
    const int b  = bq >> 5, qt = bq & 31;
    const int ql = threadIdx.x;           // 0..63
    const int nc = (qt >> 2) + 1;
    const int base = (b * 32 + qt) << 3;

    float L = 0.f;
    float acc[16];
#pragma unroll
    for (int i = 0; i < 16; i++) acc[i] = 0.f;

    for (int c = 0; c < nc; c++) {
        L += g_pl[(base + c) * 64 + ql];
        const float4* pa = reinterpret_cast<const float4*>(
            &g_pa[(size_t)((base + c) * 64 + ql) * 16]);
#pragma unroll
        for (int i = 0; i < 4; i++) {
            float4 v = pa[i];
            acc[4*i+0] += v.x;
            acc[4*i+1] += v.y;
            acc[4*i+2] += v.z;
            acc[4*i+3] += v.w;
        }
    }
    float inv = 1.0f / L;
    float4* op = reinterpret_cast<float4*>(out + ((size_t)b * NT + qt * 64 + ql) * NH);
#pragma unroll
    for (int i = 0; i < 4; i++)
        op[i] = make_float4(acc[4*i] * inv, acc[4*i+1] * inv,
                            acc[4*i+2] * inv, acc[4*i+3] * inv);
}

extern "C" void kernel_launch(void* const* d_in, const int* in_sizes, int n_in,
                              void* d_out, int out_size)
{
    const float* x  = (const float*)d_in[0];
    const float* Wq = (const float*)d_in[1];
    const float* Wk = (const float*)d_in[2];
    const float* Wv = (const float*)d_in[3];
    float* out = (float*)d_out;

    qkv_kernel<<<512, 128>>>(x, Wq, Wk, Wv);   // 256 tok-tiles x 2 col-halves
    attn_kernel<<<1152, 128>>>();              // 256-key split-K jobs, cp.async
    combine_kernel<<<256, 64>>>(out);          // sum + normalize
}